// round 16
// baseline (speedup 1.0000x reference)
#include <cuda_runtime.h>
#include <math.h>

#define B_SZ   1024
#define HID    384
#define MH     300
#define OPAD   320   // padded row stride; cols 300..319 stay zero (zero-init globals)
#define NJT    16
#define NCTA   296
#define NTASK  1440u   // 16*74 (k1 rows + k2 tiles, interleaved) + 256 k3 tiles

typedef unsigned long long u64;

// Scratch (device globals; allocations forbidden). Zero-initialized at load;
// padding columns are never written, so they remain exactly 0.0f.
__device__ float g_s1[B_SZ * HID];
__device__ float g_s2[B_SZ * HID];
__device__ float g_Axb[B_SZ * OPAD];
__device__ float g_By [B_SZ * OPAD];
__device__ float g_klpart[B_SZ];
__device__ float g_T0[B_SZ];
__device__ float g_rowpart[NJT * B_SZ];   // [jt][i]
// control state (reset by k_reset each replay)
__device__ unsigned g_task;
__device__ unsigned g_s_done[16];     // k1 rows done per row-group (target 64)
__device__ unsigned g_axb_done[16];   // k2 z=0 tiles done per row-group (target 5)
__device__ unsigned g_by_done[16];    // k2 z=1 tiles done per row-group (target 5)
__device__ unsigned g_rowdone[16];    // k3 tiles done per i-group (target 16)
__device__ unsigned g_fin;
__device__ double g_accKL, g_accT0, g_accL;

__device__ __forceinline__ float softplusf(float x) {
    return fmaxf(x, 0.f) + log1pf(expf(-fabsf(x)));
}

// Packed f32x2 ops on u64-resident data
__device__ __forceinline__ u64 f2add_u(u64 a, u64 b) {
    u64 d; asm("add.rn.f32x2 %0, %1, %2;" : "=l"(d) : "l"(a), "l"(b)); return d;
}
__device__ __forceinline__ u64 f2fma_u(u64 a, u64 b, u64 c) {
    u64 d; asm("fma.rn.f32x2 %0, %1, %2, %3;" : "=l"(d) : "l"(a), "l"(b), "l"(c)); return d;
}
__device__ __forceinline__ u64 f2relu_u(u64 a) {
    float lo, hi;
    asm("mov.b64 {%0,%1}, %2;" : "=f"(lo), "=f"(hi) : "l"(a));
    lo = fmaxf(lo, 0.f);
    hi = fmaxf(hi, 0.f);
    u64 d;
    asm("mov.b64 %0, {%1,%2};" : "=l"(d) : "f"(lo), "f"(hi));
    return d;
}
__device__ __forceinline__ float f2hsum(u64 a) {
    float lo, hi;
    asm("mov.b64 {%0,%1}, %2;" : "=f"(lo), "=f"(hi) : "l"(a));
    return lo + hi;
}
__device__ __forceinline__ u64 fpack(float x, float y) {
    u64 d; asm("mov.b64 %0, {%1,%2};" : "=l"(d) : "f"(x), "f"(y)); return d;
}

// ---------------------------------------------------------------------------
// shared-memory union across task types
// ---------------------------------------------------------------------------
struct SmemK1 {
    float z1s[768], z2s[768];
    float wls[20], wvs[36];
    float redw[8];
};
struct SmemK2 {
    u64 As[64][17];
    u64 Ws[64][17];
};
struct SmemK3 {
    u64 Bys[64][17];
    u64 Axs[64][17];
    u64 w2s[160];
    float rowred[64][17];
    double sred[3][2];
};
union SmemU {
    SmemK1 k1;
    SmemK2 k2;
    SmemK3 k3;
};

// consumer-side wait: spin on counter, gpu-fence (L1 invalidate), barrier
__device__ __forceinline__ void wait_cnt(volatile unsigned* p, unsigned tgt) {
    if (threadIdx.x == 0) {
        while (*p < tgt) __nanosleep(64);
        __threadfence();
    }
    __syncthreads();
}
__device__ __forceinline__ void wait_cnt2(volatile unsigned* p, unsigned tp,
                                          volatile unsigned* q, unsigned tq) {
    if (threadIdx.x == 0) {
        while (*p < tp || *q < tq) __nanosleep(64);
        __threadfence();
    }
    __syncthreads();
}

// ---------------------------------------------------------------------------
// reset kernel: clears all control state before each replay
// ---------------------------------------------------------------------------
__global__ void k_reset()
{
    g_task = 0u;
    g_fin = 0u;
    #pragma unroll
    for (int i = 0; i < 16; ++i) {
        g_s_done[i] = 0u; g_axb_done[i] = 0u;
        g_by_done[i] = 0u; g_rowdone[i] = 0u;
    }
    g_accKL = 0.0; g_accT0 = 0.0; g_accL = 0.0;
}

// ---------------------------------------------------------------------------
// task bodies
// ---------------------------------------------------------------------------
__device__ void task_k1(SmemK1& s, int b,
    const float* __restrict__ zl, const float* __restrict__ zv,
    const float* __restrict__ wl_g, const float* __restrict__ bl_g,
    const float* __restrict__ wv_g, const float* __restrict__ bv_g,
    const float* __restrict__ eps1, const float* __restrict__ eps2)
{
    const int t = threadIdx.x;
    if (t < 20) s.wls[t] = wl_g[t];
    if (t >= 32 && t < 68) s.wvs[t - 32] = wv_g[t - 32];
    __syncthreads();
    const float bl = bl_g[0], bv = bv_g[0];
    if (t < 192) {
        const float4* p = (const float4*)(zl + (size_t)b * 20 * 768) + t;
        float4 a = make_float4(bl, bl, bl, bl);
        #pragma unroll
        for (int sx = 0; sx < 20; ++sx) {
            float4 v = p[sx * 192];
            float w = s.wls[sx];
            a.x = fmaf(v.x, w, a.x); a.y = fmaf(v.y, w, a.y);
            a.z = fmaf(v.z, w, a.z); a.w = fmaf(v.w, w, a.w);
        }
        ((float4*)s.z1s)[t] = a;
        const float4* q = (const float4*)(zv + (size_t)b * 36 * 768) + t;
        float4 c = make_float4(bv, bv, bv, bv);
        #pragma unroll
        for (int sx = 0; sx < 36; ++sx) {
            float4 v = q[sx * 192];
            float w = s.wvs[sx];
            c.x = fmaf(v.x, w, c.x); c.y = fmaf(v.y, w, c.y);
            c.z = fmaf(v.z, w, c.z); c.w = fmaf(v.w, w, c.w);
        }
        ((float4*)s.z2s)[t] = c;
    }
    __syncthreads();
    float klacc = 0.f;
    if (t < 192) {
        #pragma unroll
        for (int q2 = 0; q2 < 2; ++q2) {
            int k = t + q2 * 192;
            float mu1 = s.z1s[k], mu2 = s.z2s[k];
            float sg1 = softplusf(s.z1s[k + HID]) + 1e-7f;
            float sg2 = softplusf(s.z2s[k + HID]) + 1e-7f;
            float e1 = eps1[b * HID + k], e2 = eps2[b * HID + k];
            float s1v = fmaf(sg1, e1, mu1);
            float s2v = fmaf(sg2, e2, mu2);
            g_s1[b * HID + k] = s1v;
            g_s2[b * HID + k] = s2v;
            float d1 = (s1v - mu2) / sg2;
            float d2 = (s2v - mu1) / sg1;
            klacc += 0.5f * (d1 * d1 + d2 * d2 - e1 * e1 - e2 * e2);
        }
    }
    #pragma unroll
    for (int off = 16; off > 0; off >>= 1)
        klacc += __shfl_xor_sync(0xFFFFFFFFu, klacc, off);
    if ((t & 31) == 0 && t < 192) s.redw[t >> 5] = klacc;
    __syncthreads();
    if (t == 0) {
        g_klpart[b] = s.redw[0] + s.redw[1] + s.redw[2]
                    + s.redw[3] + s.redw[4] + s.redw[5];
        __threadfence();
        atomicAdd(&g_s_done[b >> 6], 1u);
    }
}

__device__ void task_k2(SmemK2& s, int rg, int z, int cblk,
    const float* __restrict__ W1, const float* __restrict__ b1)
{
    wait_cnt(&g_s_done[rg], 64u);

    const int r0 = rg * 64;
    const int c0 = cblk * 64;
    const float* S = z ? g_s2 : g_s1;
    float*       O = z ? g_By : g_Axb;
    const int koff = z ? HID : 0;

    const int t  = threadIdx.x;
    const int tj = t & 15;
    const int ti = t >> 4;

    const int rP0 = t >> 3,          fP0 = t & 7;
    const int rP1 = (t + 256) >> 3,  fP1 = t & 7;
    const float* srcA0 = &S[(r0 + rP0) * HID + fP0 * 4];
    const float* srcA1 = &S[(r0 + rP1) * HID + fP1 * 4];
    const int  colW0 = c0 + rP0, colW1 = c0 + rP1;
    const bool v0 = colW0 < MH, v1 = colW1 < MH;
    const float* srcW0 = &W1[(v0 ? colW0 : 0) * 768 + koff + fP0 * 4];
    const float* srcW1 = &W1[(v1 ? colW1 : 0) * 768 + koff + fP1 * 4];

    u64 acc[4][4];
    #pragma unroll
    for (int r = 0; r < 4; ++r)
        #pragma unroll
        for (int c = 0; c < 4; ++c) acc[r][c] = 0ull;

    float4 pa0 = *(const float4*)srcA0;
    float4 pa1 = *(const float4*)srcA1;
    float4 pw0 = v0 ? *(const float4*)srcW0 : make_float4(0.f, 0.f, 0.f, 0.f);
    float4 pw1 = v1 ? *(const float4*)srcW1 : make_float4(0.f, 0.f, 0.f, 0.f);

    for (int c = 0; c < 6; ++c) {
        __syncthreads();
        s.As[rP0][2 * fP0]     = fpack(pa0.x, pa0.y);
        s.As[rP0][2 * fP0 + 1] = fpack(pa0.z, pa0.w);
        s.As[rP1][2 * fP1]     = fpack(pa1.x, pa1.y);
        s.As[rP1][2 * fP1 + 1] = fpack(pa1.z, pa1.w);
        s.Ws[rP0][2 * fP0]     = fpack(pw0.x, pw0.y);
        s.Ws[rP0][2 * fP0 + 1] = fpack(pw0.z, pw0.w);
        s.Ws[rP1][2 * fP1]     = fpack(pw1.x, pw1.y);
        s.Ws[rP1][2 * fP1 + 1] = fpack(pw1.z, pw1.w);
        __syncthreads();
        if (c < 5) {
            int off = (c + 1) * 32;
            pa0 = *(const float4*)(srcA0 + off);
            pa1 = *(const float4*)(srcA1 + off);
            pw0 = v0 ? *(const float4*)(srcW0 + off) : make_float4(0.f,0.f,0.f,0.f);
            pw1 = v1 ? *(const float4*)(srcW1 + off) : make_float4(0.f,0.f,0.f,0.f);
        }
        #pragma unroll 4
        for (int k2 = 0; k2 < 16; ++k2) {
            u64 a[4], w[4];
            #pragma unroll
            for (int r = 0; r < 4; ++r) a[r] = s.As[ti + 16 * r][k2];
            #pragma unroll
            for (int cc = 0; cc < 4; ++cc) w[cc] = s.Ws[tj + 16 * cc][k2];
            #pragma unroll
            for (int r = 0; r < 4; ++r)
                #pragma unroll
                for (int cc = 0; cc < 4; ++cc)
                    acc[r][cc] = f2fma_u(a[r], w[cc], acc[r][cc]);
        }
    }
    #pragma unroll
    for (int r = 0; r < 4; ++r) {
        int row = r0 + ti + 16 * r;
        #pragma unroll
        for (int cc = 0; cc < 4; ++cc) {
            int col = c0 + tj + 16 * cc;
            if (col < MH) {
                float v = f2hsum(acc[r][cc]);
                if (z == 0) v += b1[col];
                O[row * OPAD + col] = v;
            }
        }
    }
    __syncthreads();
    if (threadIdx.x == 0) {
        __threadfence();
        atomicAdd(z ? &g_by_done[rg] : &g_axb_done[rg], 1u);
    }
}

__device__ void task_k3(SmemK3& s, int jt, int it,
    const float* __restrict__ W2, const float* __restrict__ b2g,
    float* __restrict__ out, int* sLast)
{
    wait_cnt2(&g_by_done[it], 5u, &g_axb_done[jt], 5u);

    const int i0 = it * 64, j0 = jt * 64;
    const int t  = threadIdx.x;
    const int tj = t & 15;
    const int ti = t >> 4;

    if (t < 160) {
        int k = 2 * t;
        float2 w = make_float2(k < MH ? W2[k] : 0.f,
                               k + 1 < MH ? W2[k + 1] : 0.f);
        s.w2s[t] = *(const u64*)&w;
    }

    const int rA = t >> 3,          fA = t & 7;
    const int rB = (t + 256) >> 3,  fB = t & 7;
    const float* byA = &g_By [(i0 + rA) * OPAD + fA * 4];
    const float* byB = &g_By [(i0 + rB) * OPAD + fB * 4];
    const float* axA = &g_Axb[(j0 + rA) * OPAD + fA * 4];
    const float* axB = &g_Axb[(j0 + rB) * OPAD + fB * 4];

    u64 acc[4][4];
    #pragma unroll
    for (int r = 0; r < 4; ++r)
        #pragma unroll
        for (int c = 0; c < 4; ++c) acc[r][c] = 0ull;

    float4 pb0 = *(const float4*)(byA);
    float4 pb1 = *(const float4*)(byB);
    float4 pa0 = *(const float4*)(axA);
    float4 pa1 = *(const float4*)(axB);

    for (int c = 0; c < 10; ++c) {
        __syncthreads();
        s.Bys[rA][2 * fA]     = fpack(pb0.x, pb0.y);
        s.Bys[rA][2 * fA + 1] = fpack(pb0.z, pb0.w);
        s.Bys[rB][2 * fB]     = fpack(pb1.x, pb1.y);
        s.Bys[rB][2 * fB + 1] = fpack(pb1.z, pb1.w);
        s.Axs[rA][2 * fA]     = fpack(pa0.x, pa0.y);
        s.Axs[rA][2 * fA + 1] = fpack(pa0.z, pa0.w);
        s.Axs[rB][2 * fB]     = fpack(pa1.x, pa1.y);
        s.Axs[rB][2 * fB + 1] = fpack(pa1.z, pa1.w);
        __syncthreads();
        if (c < 9) {
            int off = (c + 1) * 32;
            pb0 = *(const float4*)(byA + off);
            pb1 = *(const float4*)(byB + off);
            pa0 = *(const float4*)(axA + off);
            pa1 = *(const float4*)(axB + off);
        }
        #pragma unroll 4
        for (int k2 = 0; k2 < 16; ++k2) {
            u64 wp = s.w2s[c * 16 + k2];
            u64 a[4], b[4];
            #pragma unroll
            for (int cc = 0; cc < 4; ++cc) a[cc] = s.Axs[tj + 16 * cc][k2];
            #pragma unroll
            for (int r = 0; r < 4; ++r) b[r] = s.Bys[ti + 16 * r][k2];
            #pragma unroll
            for (int r = 0; r < 4; ++r)
                #pragma unroll
                for (int cc = 0; cc < 4; ++cc)
                    acc[r][cc] = f2fma_u(f2relu_u(f2add_u(a[cc], b[r])), wp,
                                         acc[r][cc]);
        }
    }

    const float b2v = b2g[0];

    if (jt == it && tj == ti) {
        #pragma unroll
        for (int r = 0; r < 4; ++r)
            g_T0[i0 + ti + 16 * r] = softplusf(f2hsum(acc[r][r]) + b2v);
    }

    __syncthreads();
    #pragma unroll
    for (int r = 0; r < 4; ++r) {
        float e = 0.f;
        #pragma unroll
        for (int cc = 0; cc < 4; ++cc)
            e += expf(f2hsum(acc[r][cc]) + b2v);
        s.rowred[ti + 16 * r][tj] = e;
    }
    __syncthreads();
    if (t < 64) {
        float sum = 0.f;
        #pragma unroll
        for (int cc = 0; cc < 16; ++cc) sum += s.rowred[t][cc];
        g_rowpart[jt * B_SZ + i0 + t] = sum;
    }

    // ---- row-group finisher ----
    __threadfence();
    __syncthreads();
    if (t == 0) {
        unsigned old = atomicAdd(&g_rowdone[it], 1u);
        *sLast = (old == 15u);
    }
    __syncthreads();
    if (*sLast) {
        __threadfence();   // acquire: all 16 CTAs' rowpart/T0 writes visible
        double kl = 0.0, t0 = 0.0, L = 0.0;
        if (t < 64) {
            int i = i0 + t;
            float rs = 0.f;
            #pragma unroll
            for (int j = 0; j < NJT; ++j)
                rs += g_rowpart[j * B_SZ + i];
            kl = (double)g_klpart[i];
            t0 = (double)g_T0[i];
            // logsumexp_j softplus(u) = log(B + sum_j e^u)
            L  = (double)logf((float)B_SZ + rs);
        }
        if (t < 64) {
            #pragma unroll
            for (int off = 16; off > 0; off >>= 1) {
                kl += __shfl_xor_sync(0xFFFFFFFFu, kl, off);
                t0 += __shfl_xor_sync(0xFFFFFFFFu, t0, off);
                L  += __shfl_xor_sync(0xFFFFFFFFu, L,  off);
            }
            if ((t & 31) == 0) {
                s.sred[0][t >> 5] = kl;
                s.sred[1][t >> 5] = t0;
                s.sred[2][t >> 5] = L;
            }
        }
        __syncthreads();
        if (t == 0) {
            atomicAdd(&g_accKL, s.sred[0][0] + s.sred[0][1]);
            atomicAdd(&g_accT0, s.sred[1][0] + s.sred[1][1]);
            atomicAdd(&g_accL,  s.sred[2][0] + s.sred[2][1]);
            __threadfence();
            unsigned old = atomicAdd(&g_fin, 1u);
            if (old == 15u) {
                __threadfence();
                double a = g_accKL, b = g_accT0, c = g_accL;
                double d_skl = a / (double)B_SZ * 0.5;
                double t0m   = b / (double)B_SZ;
                double meanL = c / (double)B_SZ;
                double lower = t0m - (meanL - log((double)B_SZ));
                out[0] = (float)(d_skl - lower);
            }
        }
        __syncthreads();
    }
}

// ---------------------------------------------------------------------------
// fused persistent kernel: 296 CTAs pull tasks in topological order
// ---------------------------------------------------------------------------
__global__ __launch_bounds__(256, 2) void k_fused(
    const float* __restrict__ zl, const float* __restrict__ zv,
    const float* __restrict__ wl_g, const float* __restrict__ bl_g,
    const float* __restrict__ wv_g, const float* __restrict__ bv_g,
    const float* __restrict__ W1, const float* __restrict__ b1,
    const float* __restrict__ W2, const float* __restrict__ b2g,
    const float* __restrict__ eps1, const float* __restrict__ eps2,
    float* __restrict__ out)
{
    __shared__ SmemU sm;
    __shared__ unsigned sTask;
    __shared__ int sLast;

    for (;;) {
        __syncthreads();   // protect smem union reuse + sTask
        if (threadIdx.x == 0) sTask = atomicAdd(&g_task, 1u);
        __syncthreads();
        const unsigned id = sTask;
        if (id >= NTASK) break;

        if (id < 1184u) {
            const int g = (int)(id / 74u);
            const int l = (int)(id % 74u);
            if (l < 64) {
                task_k1(sm.k1, g * 64 + l,
                        zl, zv, wl_g, bl_g, wv_g, bv_g, eps1, eps2);
            } else {
                const int m = l - 64;
                task_k2(sm.k2, g, m / 5, m % 5, W1, b1);
            }
        } else {
            const int n = (int)(id - 1184u);
            int sdiag = (int)sqrtf((float)n);
            while ((sdiag + 1) * (sdiag + 1) <= n) ++sdiag;
            while (sdiag * sdiag > n) --sdiag;
            const int r = n - sdiag * sdiag;
            int it, jt;
            if (r == 0) { it = sdiag; jt = sdiag; }
            else {
                const int k = (r - 1) >> 1;
                if ((r - 1) & 1) { it = sdiag; jt = k; }
                else             { it = k; jt = sdiag; }
            }
            task_k3(sm.k3, jt, it, W2, b2g, out, &sLast);
        }
    }
}

// ---------------------------------------------------------------------------
extern "C" void kernel_launch(void* const* d_in, const int* in_sizes, int n_in,
                              void* d_out, int out_size)
{
    const float* zl    = (const float*)d_in[0];
    const float* zv    = (const float*)d_in[1];
    const float* fclw  = (const float*)d_in[2];
    const float* fclb  = (const float*)d_in[3];
    const float* fcvw  = (const float*)d_in[4];
    const float* fcvb  = (const float*)d_in[5];
    const float* W1    = (const float*)d_in[6];
    const float* b1    = (const float*)d_in[7];
    const float* W2    = (const float*)d_in[8];
    const float* b2    = (const float*)d_in[9];
    const float* eps1  = (const float*)d_in[10];
    const float* eps2  = (const float*)d_in[11];
    float* out = (float*)d_out;

    k_reset<<<1, 1>>>();
    k_fused<<<NCTA, 256>>>(zl, zv, fclw, fclb, fcvw, fcvb,
                           W1, b1, W2, b2, eps1, eps2, out);
}